// round 2
// baseline (speedup 1.0000x reference)
#include <cuda_runtime.h>

// SpikeFP32LayerNorm: row-wise LayerNorm (no affine) over 8192 rows x 4096 fp32.
// Persistent-CTA version: grid of 592 CTAs, each loops over rows with a
// one-row-deep register prefetch pipeline so DRAM loads for row r+1 overlap
// the reduction + store of row r. Streaming cache hints (touch-once data).

#define ROWS  8192
#define NCOLS 4096
#define TPB   512           // 16 warps; each thread owns 2x float4 of a row
#define GRID  592           // 148 SMs x 4 resident-CTA slots worth of work

__global__ __launch_bounds__(TPB, 3)
void spike_ln_persistent(const float* __restrict__ x, float* __restrict__ out) {
    const int tid = threadIdx.x;
    const int wid = tid >> 5;
    const int lid = tid & 31;

    __shared__ float ssum[16];
    __shared__ float ssq[16];
    __shared__ float s_mean, s_rstd;

    int row = blockIdx.x;

    // Prime the pipeline: load first row into registers.
    const float4* __restrict__ xin =
        reinterpret_cast<const float4*>(x + (size_t)row * NCOLS);
    float4 v0 = __ldcs(&xin[tid]);
    float4 v1 = __ldcs(&xin[tid + TPB]);

    while (row < ROWS) {
        // ---- reduction over the row held in registers ----
        float s  = (v0.x + v0.y) + (v0.z + v0.w) + (v1.x + v1.y) + (v1.z + v1.w);
        float sq = v0.x * v0.x + v0.y * v0.y + v0.z * v0.z + v0.w * v0.w
                 + v1.x * v1.x + v1.y * v1.y + v1.z * v1.z + v1.w * v1.w;

        #pragma unroll
        for (int off = 16; off > 0; off >>= 1) {
            s  += __shfl_xor_sync(0xFFFFFFFFu, s,  off);
            sq += __shfl_xor_sync(0xFFFFFFFFu, sq, off);
        }
        if (lid == 0) { ssum[wid] = s; ssq[wid] = sq; }
        __syncthreads();

        if (wid == 0) {
            float ts  = (lid < 16) ? ssum[lid] : 0.0f;
            float tsq = (lid < 16) ? ssq[lid]  : 0.0f;
            #pragma unroll
            for (int off = 8; off > 0; off >>= 1) {
                ts  += __shfl_xor_sync(0xFFFFFFFFu, ts,  off);
                tsq += __shfl_xor_sync(0xFFFFFFFFu, tsq, off);
            }
            if (lid == 0) {
                const float inv_n = 1.0f / (float)NCOLS;
                float mean = ts * inv_n;
                float var  = fmaxf(tsq * inv_n - mean * mean, 0.0f);
                float vpe  = var + 1e-6f;
                float y = rsqrtf(vpe);
                y = 0.5f * y * (3.0f - vpe * (y * y));   // one NR polish
                s_mean = mean;
                s_rstd = y;
            }
        }
        __syncthreads();

        const float mean = s_mean;
        const float rstd = s_rstd;

        // ---- prefetch next row BEFORE storing this one ----
        const int next = row + GRID;
        float4 w0, w1;
        if (next < ROWS) {
            const float4* __restrict__ xin2 =
                reinterpret_cast<const float4*>(x + (size_t)next * NCOLS);
            w0 = __ldcs(&xin2[tid]);
            w1 = __ldcs(&xin2[tid + TPB]);
        }

        // ---- normalize + streaming store of current row ----
        float4* __restrict__ xout =
            reinterpret_cast<float4*>(out + (size_t)row * NCOLS);
        float4 o0, o1;
        o0.x = (v0.x - mean) * rstd;  o0.y = (v0.y - mean) * rstd;
        o0.z = (v0.z - mean) * rstd;  o0.w = (v0.w - mean) * rstd;
        o1.x = (v1.x - mean) * rstd;  o1.y = (v1.y - mean) * rstd;
        o1.z = (v1.z - mean) * rstd;  o1.w = (v1.w - mean) * rstd;
        __stcs(&xout[tid],       o0);
        __stcs(&xout[tid + TPB], o1);

        v0 = w0;
        v1 = w1;
        row = next;
    }
}

extern "C" void kernel_launch(void* const* d_in, const int* in_sizes, int n_in,
                              void* d_out, int out_size) {
    const float* x = (const float*)d_in[0];
    float* out = (float*)d_out;
    spike_ln_persistent<<<GRID, TPB>>>(x, out);
}

// round 3
// speedup vs baseline: 1.0283x; 1.0283x over previous
#include <cuda_runtime.h>

// SpikeFP32LayerNorm: row-wise LayerNorm (no affine) over 8192 rows x 4096 fp32.
// One CTA per row (best-measured config). Row held in registers (2x float4 per
// thread), single-barrier reduction (warp partials -> smem -> every thread
// redundantly reduces 16 values, no second barrier/broadcast), streaming
// load/store hints. This workload is at the LTS chip cap (~7 TB/s effective).

#define ROWS  8192
#define NCOLS 4096
#define TPB   512          // 16 warps; each thread owns 2x float4 of a row

__global__ __launch_bounds__(TPB, 4)
void spike_ln_kernel(const float* __restrict__ x, float* __restrict__ out) {
    const int tid = threadIdx.x;
    const int row = blockIdx.x;

    const float4* __restrict__ xin =
        reinterpret_cast<const float4*>(x + (size_t)row * NCOLS);
    float4* __restrict__ xout =
        reinterpret_cast<float4*>(out + (size_t)row * NCOLS);

    // Two independent 128-bit streaming loads (coalesced; MLP=2)
    float4 v0 = __ldcs(&xin[tid]);
    float4 v1 = __ldcs(&xin[tid + TPB]);

    float s  = (v0.x + v0.y) + (v0.z + v0.w) + (v1.x + v1.y) + (v1.z + v1.w);
    float sq = v0.x * v0.x + v0.y * v0.y + v0.z * v0.z + v0.w * v0.w
             + v1.x * v1.x + v1.y * v1.y + v1.z * v1.z + v1.w * v1.w;

    // Warp reduction of both accumulators
    #pragma unroll
    for (int off = 16; off > 0; off >>= 1) {
        s  += __shfl_xor_sync(0xFFFFFFFFu, s,  off);
        sq += __shfl_xor_sync(0xFFFFFFFFu, sq, off);
    }

    // float2 per warp: {sum, sumsq}
    __shared__ float2 spart[16];
    const int wid = tid >> 5;
    const int lid = tid & 31;
    if (lid == 0) spart[wid] = make_float2(s, sq);
    __syncthreads();

    // Every thread redundantly reduces the 16 partials: no 2nd barrier,
    // no broadcast round-trip. 16 LDS.64 + adds + 1 MUFU per thread.
    float ts = 0.0f, tsq = 0.0f;
    #pragma unroll
    for (int i = 0; i < 16; i++) {
        float2 p = spart[i];
        ts  += p.x;
        tsq += p.y;
    }

    const float inv_n = 1.0f / (float)NCOLS;
    const float mean  = ts * inv_n;
    float var = fmaxf(tsq * inv_n - mean * mean, 0.0f);
    float vpe = var + 1e-6f;
    float rstd = rsqrtf(vpe);
    rstd = 0.5f * rstd * (3.0f - vpe * (rstd * rstd));  // one NR polish

    float4 o0, o1;
    o0.x = (v0.x - mean) * rstd;  o0.y = (v0.y - mean) * rstd;
    o0.z = (v0.z - mean) * rstd;  o0.w = (v0.w - mean) * rstd;
    o1.x = (v1.x - mean) * rstd;  o1.y = (v1.y - mean) * rstd;
    o1.z = (v1.z - mean) * rstd;  o1.w = (v1.w - mean) * rstd;

    __stcs(&xout[tid],       o0);
    __stcs(&xout[tid + TPB], o1);
}

extern "C" void kernel_launch(void* const* d_in, const int* in_sizes, int n_in,
                              void* d_out, int out_size) {
    const float* x = (const float*)d_in[0];
    float* out = (float*)d_out;
    spike_ln_kernel<<<ROWS, TPB>>>(x, out);
}

// round 4
// speedup vs baseline: 1.0342x; 1.0057x over previous
#include <cuda_runtime.h>

// SpikeFP32LayerNorm: row-wise LayerNorm (no affine) over 8192 rows x 4096 fp32.
// Best-measured configuration (R1): one CTA per row, 512 threads, row held in
// registers (2x float4/thread), two-stage shuffle+smem reduction, rsqrt+1 NR.
// Only delta vs R1: streaming store hint (output is touch-once; keep L2 for
// in-flight input reads). Workload is at the LTS/HBM wall (~7 TB/s effective).

#define ROWS  8192
#define NCOLS 4096
#define TPB   512            // 16 warps

__global__ __launch_bounds__(TPB, 4)
void spike_ln_kernel(const float* __restrict__ x, float* __restrict__ out) {
    const int row = blockIdx.x;
    const float4* __restrict__ xin =
        reinterpret_cast<const float4*>(x + (size_t)row * NCOLS);
    float4* __restrict__ xout =
        reinterpret_cast<float4*>(out + (size_t)row * NCOLS);

    // Two independent 128-bit loads per thread (coalesced; MLP=2)
    float4 v0 = xin[threadIdx.x];
    float4 v1 = xin[threadIdx.x + TPB];

    float s  = (v0.x + v0.y) + (v0.z + v0.w) + (v1.x + v1.y) + (v1.z + v1.w);
    float sq = v0.x * v0.x + v0.y * v0.y + v0.z * v0.z + v0.w * v0.w
             + v1.x * v1.x + v1.y * v1.y + v1.z * v1.z + v1.w * v1.w;

    // Warp reduction of both accumulators
    #pragma unroll
    for (int off = 16; off > 0; off >>= 1) {
        s  += __shfl_xor_sync(0xFFFFFFFFu, s,  off);
        sq += __shfl_xor_sync(0xFFFFFFFFu, sq, off);
    }

    __shared__ float ssum[16];
    __shared__ float ssq[16];
    __shared__ float s_mean, s_rstd;

    const int wid = threadIdx.x >> 5;
    const int lid = threadIdx.x & 31;
    if (lid == 0) { ssum[wid] = s; ssq[wid] = sq; }
    __syncthreads();

    if (wid == 0) {
        float ts  = (lid < 16) ? ssum[lid] : 0.0f;
        float tsq = (lid < 16) ? ssq[lid]  : 0.0f;
        #pragma unroll
        for (int off = 8; off > 0; off >>= 1) {
            ts  += __shfl_xor_sync(0xFFFFFFFFu, ts,  off);
            tsq += __shfl_xor_sync(0xFFFFFFFFu, tsq, off);
        }
        if (lid == 0) {
            const float inv_n = 1.0f / (float)NCOLS;
            float mean = ts * inv_n;
            float var  = fmaxf(tsq * inv_n - mean * mean, 0.0f);
            float vpe  = var + 1e-6f;
            float y = rsqrtf(vpe);
            y = 0.5f * y * (3.0f - vpe * (y * y));   // one NR polish
            s_mean = mean;
            s_rstd = y;
        }
    }
    __syncthreads();

    const float mean = s_mean;
    const float rstd = s_rstd;

    float4 o0, o1;
    o0.x = (v0.x - mean) * rstd;  o0.y = (v0.y - mean) * rstd;
    o0.z = (v0.z - mean) * rstd;  o0.w = (v0.w - mean) * rstd;
    o1.x = (v1.x - mean) * rstd;  o1.y = (v1.y - mean) * rstd;
    o1.z = (v1.z - mean) * rstd;  o1.w = (v1.w - mean) * rstd;

    __stcs(&xout[threadIdx.x],       o0);
    __stcs(&xout[threadIdx.x + TPB], o1);
}

extern "C" void kernel_launch(void* const* d_in, const int* in_sizes, int n_in,
                              void* d_out, int out_size) {
    const float* x = (const float*)d_in[0];
    float* out = (float*)d_out;
    spike_ln_kernel<<<ROWS, TPB>>>(x, out);
}

// round 5
// speedup vs baseline: 1.0372x; 1.0029x over previous
#include <cuda_runtime.h>

// SpikeFP32LayerNorm: row-wise LayerNorm (no affine) over 8192 rows x 4096 fp32.
// 256 threads/CTA, one row/CTA: each thread owns 4x float4 (64 B) giving
// MLP_p1=4 front-batched 128-bit loads, 8-warp reduction tree, rsqrt + 1 NR.
// Workload is at the HBM wall (~7 TB/s aggregate); this variant maximizes
// per-thread memory-level parallelism within that budget.

#define ROWS  8192
#define NCOLS 4096
#define TPB   256            // 8 warps; 4x float4 per thread

__global__ __launch_bounds__(TPB, 6)
void spike_ln_kernel(const float* __restrict__ x, float* __restrict__ out) {
    const int tid = threadIdx.x;
    const int row = blockIdx.x;
    const float4* __restrict__ xin =
        reinterpret_cast<const float4*>(x + (size_t)row * NCOLS);
    float4* __restrict__ xout =
        reinterpret_cast<float4*>(out + (size_t)row * NCOLS);

    // Four independent 128-bit loads per thread (coalesced; MLP_p1=4)
    float4 v0 = xin[tid];
    float4 v1 = xin[tid + TPB];
    float4 v2 = xin[tid + 2 * TPB];
    float4 v3 = xin[tid + 3 * TPB];

    float s  = ((v0.x + v0.y) + (v0.z + v0.w)) + ((v1.x + v1.y) + (v1.z + v1.w))
             + ((v2.x + v2.y) + (v2.z + v2.w)) + ((v3.x + v3.y) + (v3.z + v3.w));
    float sq = v0.x * v0.x + v0.y * v0.y + v0.z * v0.z + v0.w * v0.w
             + v1.x * v1.x + v1.y * v1.y + v1.z * v1.z + v1.w * v1.w
             + v2.x * v2.x + v2.y * v2.y + v2.z * v2.z + v2.w * v2.w
             + v3.x * v3.x + v3.y * v3.y + v3.z * v3.z + v3.w * v3.w;

    // Warp reduction of both accumulators
    #pragma unroll
    for (int off = 16; off > 0; off >>= 1) {
        s  += __shfl_xor_sync(0xFFFFFFFFu, s,  off);
        sq += __shfl_xor_sync(0xFFFFFFFFu, sq, off);
    }

    __shared__ float ssum[8];
    __shared__ float ssq[8];
    __shared__ float s_mean, s_rstd;

    const int wid = tid >> 5;
    const int lid = tid & 31;
    if (lid == 0) { ssum[wid] = s; ssq[wid] = sq; }
    __syncthreads();

    if (wid == 0) {
        float ts  = (lid < 8) ? ssum[lid] : 0.0f;
        float tsq = (lid < 8) ? ssq[lid]  : 0.0f;
        #pragma unroll
        for (int off = 4; off > 0; off >>= 1) {
            ts  += __shfl_xor_sync(0xFFFFFFFFu, ts,  off);
            tsq += __shfl_xor_sync(0xFFFFFFFFu, tsq, off);
        }
        if (lid == 0) {
            const float inv_n = 1.0f / (float)NCOLS;
            float mean = ts * inv_n;
            float var  = fmaxf(tsq * inv_n - mean * mean, 0.0f);
            float vpe  = var + 1e-6f;
            float y = rsqrtf(vpe);
            y = 0.5f * y * (3.0f - vpe * (y * y));   // one NR polish
            s_mean = mean;
            s_rstd = y;
        }
    }
    __syncthreads();

    const float mean = s_mean;
    const float rstd = s_rstd;

    float4 o0, o1, o2, o3;
    o0.x = (v0.x - mean) * rstd;  o0.y = (v0.y - mean) * rstd;
    o0.z = (v0.z - mean) * rstd;  o0.w = (v0.w - mean) * rstd;
    o1.x = (v1.x - mean) * rstd;  o1.y = (v1.y - mean) * rstd;
    o1.z = (v1.z - mean) * rstd;  o1.w = (v1.w - mean) * rstd;
    o2.x = (v2.x - mean) * rstd;  o2.y = (v2.y - mean) * rstd;
    o2.z = (v2.z - mean) * rstd;  o2.w = (v2.w - mean) * rstd;
    o3.x = (v3.x - mean) * rstd;  o3.y = (v3.y - mean) * rstd;
    o3.z = (v3.z - mean) * rstd;  o3.w = (v3.w - mean) * rstd;

    __stcs(&xout[tid],           o0);
    __stcs(&xout[tid + TPB],     o1);
    __stcs(&xout[tid + 2 * TPB], o2);
    __stcs(&xout[tid + 3 * TPB], o3);
}

extern "C" void kernel_launch(void* const* d_in, const int* in_sizes, int n_in,
                              void* d_out, int out_size) {
    const float* x = (const float*)d_in[0];
    float* out = (float*)d_out;
    spike_ln_kernel<<<ROWS, TPB>>>(x, out);
}

// round 6
// speedup vs baseline: 1.0669x; 1.0287x over previous
#include <cuda_runtime.h>

// SpikeFP32LayerNorm: row-wise LayerNorm (no affine) over 8192 rows x 4096 fp32.
// 128 threads/CTA, one row/CTA: each thread owns 8x float4 (128 B = one L2
// line) giving MLP_p1=8 front-batched 128-bit loads. 4-warp reduction tree,
// rsqrt + 1 NR. Scaling DRAM% by raising per-thread memory-level parallelism
// (MLP 2->4 already gave 38.2->36.0 us).

#define ROWS  8192
#define NCOLS 4096
#define TPB   128            // 4 warps; 8x float4 per thread
#define NV    8              // float4s per thread

__global__ __launch_bounds__(TPB, 10)
void spike_ln_kernel(const float* __restrict__ x, float* __restrict__ out) {
    const int tid = threadIdx.x;
    const int row = blockIdx.x;
    const float4* __restrict__ xin =
        reinterpret_cast<const float4*>(x + (size_t)row * NCOLS);
    float4* __restrict__ xout =
        reinterpret_cast<float4*>(out + (size_t)row * NCOLS);

    // Eight independent 128-bit loads per thread (coalesced; MLP_p1=8)
    float4 v[NV];
    #pragma unroll
    for (int i = 0; i < NV; i++)
        v[i] = xin[tid + i * TPB];

    // Two independent accumulator pairs to shorten the FADD dependence chain
    float s0 = 0.0f, s1 = 0.0f, q0 = 0.0f, q1 = 0.0f;
    #pragma unroll
    for (int i = 0; i < NV; i += 2) {
        s0 += (v[i].x + v[i].y) + (v[i].z + v[i].w);
        q0 += v[i].x * v[i].x + v[i].y * v[i].y + v[i].z * v[i].z + v[i].w * v[i].w;
        s1 += (v[i+1].x + v[i+1].y) + (v[i+1].z + v[i+1].w);
        q1 += v[i+1].x * v[i+1].x + v[i+1].y * v[i+1].y
            + v[i+1].z * v[i+1].z + v[i+1].w * v[i+1].w;
    }
    float s  = s0 + s1;
    float sq = q0 + q1;

    // Warp reduction of both accumulators
    #pragma unroll
    for (int off = 16; off > 0; off >>= 1) {
        s  += __shfl_xor_sync(0xFFFFFFFFu, s,  off);
        sq += __shfl_xor_sync(0xFFFFFFFFu, sq, off);
    }

    __shared__ float ssum[4];
    __shared__ float ssq[4];
    __shared__ float s_mean, s_rstd;

    const int wid = tid >> 5;
    const int lid = tid & 31;
    if (lid == 0) { ssum[wid] = s; ssq[wid] = sq; }
    __syncthreads();

    if (wid == 0) {
        float ts  = (lid < 4) ? ssum[lid] : 0.0f;
        float tsq = (lid < 4) ? ssq[lid]  : 0.0f;
        #pragma unroll
        for (int off = 2; off > 0; off >>= 1) {
            ts  += __shfl_xor_sync(0xFFFFFFFFu, ts,  off);
            tsq += __shfl_xor_sync(0xFFFFFFFFu, tsq, off);
        }
        if (lid == 0) {
            const float inv_n = 1.0f / (float)NCOLS;
            float mean = ts * inv_n;
            float var  = fmaxf(tsq * inv_n - mean * mean, 0.0f);
            float vpe  = var + 1e-6f;
            float y = rsqrtf(vpe);
            y = 0.5f * y * (3.0f - vpe * (y * y));   // one NR polish
            s_mean = mean;
            s_rstd = y;
        }
    }
    __syncthreads();

    const float mean = s_mean;
    const float rstd = s_rstd;

    #pragma unroll
    for (int i = 0; i < NV; i++) {
        float4 o;
        o.x = (v[i].x - mean) * rstd;
        o.y = (v[i].y - mean) * rstd;
        o.z = (v[i].z - mean) * rstd;
        o.w = (v[i].w - mean) * rstd;
        __stcs(&xout[tid + i * TPB], o);
    }
}

extern "C" void kernel_launch(void* const* d_in, const int* in_sizes, int n_in,
                              void* d_out, int out_size) {
    const float* x = (const float*)d_in[0];
    float* out = (float*)d_out;
    spike_ln_kernel<<<ROWS, TPB>>>(x, out);
}